// round 2
// baseline (speedup 1.0000x reference)
#include <cuda_runtime.h>
#include <math.h>

// Problem constants
#define NTOK 8192          // B*S
#define DD   1024          // D
#define EE   8             // experts
#define BM   128
#define BN   128
#define BK   16
#define AS_STRIDE 132
#define BS_STRIDE 132

// Routing scratch (allocation-free: __device__ globals)
__device__ int   g_cnt[EE];
__device__ int   g_tok[EE * NTOK];
__device__ float g_wt [EE * NTOK];

// ---------------------------------------------------------------------------
// packed f32x2 helpers
// ---------------------------------------------------------------------------
__device__ __forceinline__ unsigned long long pack2(float lo, float hi) {
    unsigned long long r;
    asm("mov.b64 %0, {%1, %2};" : "=l"(r) : "f"(lo), "f"(hi));
    return r;
}
__device__ __forceinline__ void unpack2(unsigned long long v, float& lo, float& hi) {
    asm("mov.b64 {%0, %1}, %2;" : "=f"(lo), "=f"(hi) : "l"(v));
}
__device__ __forceinline__ void ffma2(unsigned long long& c,
                                      unsigned long long a,
                                      unsigned long long b) {
    asm("fma.rn.f32x2 %0, %1, %2, %0;" : "+l"(c) : "l"(a), "l"(b));
}

// ---------------------------------------------------------------------------
// reset routing counters (runs every launch; graph-capturable)
// ---------------------------------------------------------------------------
__global__ void reset_kernel() {
    if (threadIdx.x < EE) g_cnt[threadIdx.x] = 0;
}

// ---------------------------------------------------------------------------
// Gating: one warp per token. scores = x @ Wg + bg; top-2; 2-way softmax;
// route (token, weight) into per-expert lists.
// ---------------------------------------------------------------------------
__global__ void gate_kernel(const float* __restrict__ x,
                            const float* __restrict__ Wg,
                            const float* __restrict__ bg) {
    int gwarp = (blockIdx.x * blockDim.x + threadIdx.x) >> 5;
    int lane  = threadIdx.x & 31;
    if (gwarp >= NTOK) return;

    const float* xr = x + (size_t)gwarp * DD;

    float acc[EE];
#pragma unroll
    for (int e = 0; e < EE; e++) acc[e] = 0.f;

    for (int d = lane; d < DD; d += 32) {
        float xv = xr[d];
        const float4* wr = reinterpret_cast<const float4*>(Wg + (size_t)d * EE);
        float4 w0 = wr[0];
        float4 w1 = wr[1];
        acc[0] += xv * w0.x; acc[1] += xv * w0.y;
        acc[2] += xv * w0.z; acc[3] += xv * w0.w;
        acc[4] += xv * w1.x; acc[5] += xv * w1.y;
        acc[6] += xv * w1.z; acc[7] += xv * w1.w;
    }
#pragma unroll
    for (int e = 0; e < EE; e++) {
#pragma unroll
        for (int off = 16; off > 0; off >>= 1)
            acc[e] += __shfl_xor_sync(0xffffffffu, acc[e], off);
    }

    if (lane == 0) {
        float s[EE];
#pragma unroll
        for (int e = 0; e < EE; e++) s[e] = acc[e] + bg[e];

        int i0 = 0;
#pragma unroll
        for (int e = 1; e < EE; e++) if (s[e] > s[i0]) i0 = e;
        int i1 = (i0 == 0) ? 1 : 0;
#pragma unroll
        for (int e = 0; e < EE; e++) if (e != i0 && s[e] > s[i1]) i1 = e;

        // softmax over {s[i0], s[i1]} with everything else masked to -inf
        float w0 = 1.f / (1.f + expf(s[i1] - s[i0]));
        float w1 = 1.f - w0;

        int p0 = atomicAdd(&g_cnt[i0], 1);
        g_tok[i0 * NTOK + p0] = gwarp;
        g_wt [i0 * NTOK + p0] = w0;
        int p1 = atomicAdd(&g_cnt[i1], 1);
        g_tok[i1 * NTOK + p1] = gwarp;
        g_wt [i1 * NTOK + p1] = w1;
    }
}

// ---------------------------------------------------------------------------
// Grouped GEMM: for expert e, Y = gather(X, toks) @ We[e]; epilogue does
// out[tok, n] += w * (Y + be[e, n])  via atomicAdd (exactly 2 contribs/elem,
// order-independent for 2-operand fp adds -> deterministic).
// grid: (BN tiles = 8, worst-case BM tiles = 64, experts = 8)
// ---------------------------------------------------------------------------
__global__ void __launch_bounds__(256, 2)
moe_gemm(const float* __restrict__ x,
         const float* __restrict__ We,
         const float* __restrict__ be,
         float* __restrict__ out) {
    int e   = blockIdx.z;
    int cnt = g_cnt[e];
    int m0  = blockIdx.y * BM;
    if (m0 >= cnt) return;
    int rows = min(BM, cnt - m0);
    int n0   = blockIdx.x * BN;

    __shared__ float As[BK][AS_STRIDE];
    __shared__ float Bs[BK][BS_STRIDE];
    __shared__ int   stok[BM];
    __shared__ float swt[BM];

    int tid = threadIdx.x;
    if (tid < BM) {
        int r = (tid < rows) ? tid : 0;   // clamp for safe gather addresses
        stok[tid] = g_tok[e * NTOK + m0 + r];
        swt [tid] = (tid < rows) ? g_wt[e * NTOK + m0 + tid] : 0.f;
    }
    __syncthreads();

    const float* Wbase = We + (size_t)e * DD * DD + n0;

    // ---- loader mapping ----
    // A: thread loads two float4 x-segments (passes m and m+64)
    int a_m   = tid >> 2;            // 0..63
    int a_k4  = (tid & 3) * 4;       // 0,4,8,12
    const float* arow0 = x + (size_t)stok[a_m]       * DD + a_k4;
    const float* arow1 = x + (size_t)stok[a_m + 64]  * DD + a_k4;
    // B: thread loads two float4 rows of We (n and n+64)
    int b_kk  = tid >> 4;            // 0..15
    int b_n4  = (tid & 15) * 4;      // 0..60
    const float* brow = Wbase + (size_t)b_kk * DD + b_n4;

    // ---- compute mapping ----
    int tx = tid & 15;               // n groups: tx*4 .. +3 and 64+tx*4 .. +3
    int ty = tid >> 4;               // m groups: ty*4 .. +3 and 64+ty*4 .. +3

    unsigned long long c[8][4];
#pragma unroll
    for (int i = 0; i < 8; i++)
#pragma unroll
        for (int j = 0; j < 4; j++) c[i][j] = 0ULL;

    for (int k = 0; k < DD; k += BK) {
        float4 av0 = *reinterpret_cast<const float4*>(arow0 + k);
        float4 av1 = *reinterpret_cast<const float4*>(arow1 + k);
        float4 bv0 = *reinterpret_cast<const float4*>(brow + (size_t)k * DD);
        float4 bv1 = *reinterpret_cast<const float4*>(brow + (size_t)k * DD + 64);

        __syncthreads();   // previous iteration's compute done

        As[a_k4 + 0][a_m] = av0.x; As[a_k4 + 1][a_m] = av0.y;
        As[a_k4 + 2][a_m] = av0.z; As[a_k4 + 3][a_m] = av0.w;
        As[a_k4 + 0][a_m + 64] = av1.x; As[a_k4 + 1][a_m + 64] = av1.y;
        As[a_k4 + 2][a_m + 64] = av1.z; As[a_k4 + 3][a_m + 64] = av1.w;
        *reinterpret_cast<float4*>(&Bs[b_kk][b_n4])      = bv0;
        *reinterpret_cast<float4*>(&Bs[b_kk][b_n4 + 64]) = bv1;

        __syncthreads();

#pragma unroll
        for (int kk = 0; kk < BK; kk++) {
            float4 am0 = *reinterpret_cast<const float4*>(&As[kk][ty * 4]);
            float4 am1 = *reinterpret_cast<const float4*>(&As[kk][64 + ty * 4]);
            float4 bn0 = *reinterpret_cast<const float4*>(&Bs[kk][tx * 4]);
            float4 bn1 = *reinterpret_cast<const float4*>(&Bs[kk][64 + tx * 4]);

            unsigned long long b2[4];
            b2[0] = pack2(bn0.x, bn0.y);
            b2[1] = pack2(bn0.z, bn0.w);
            b2[2] = pack2(bn1.x, bn1.y);
            b2[3] = pack2(bn1.z, bn1.w);

            float a[8] = {am0.x, am0.y, am0.z, am0.w,
                          am1.x, am1.y, am1.z, am1.w};
#pragma unroll
            for (int i = 0; i < 8; i++) {
                unsigned long long ad = pack2(a[i], a[i]);
#pragma unroll
                for (int j = 0; j < 4; j++) ffma2(c[i][j], ad, b2[j]);
            }
        }
    }

    // ---- epilogue: out[tok, n] += w * (acc + be[e, n]) ----
    const float* berow = be + (size_t)e * DD + n0;
    float4 be0 = *reinterpret_cast<const float4*>(berow + tx * 4);
    float4 be1 = *reinterpret_cast<const float4*>(berow + 64 + tx * 4);
    float bev[8] = {be0.x, be0.y, be0.z, be0.w, be1.x, be1.y, be1.z, be1.w};

#pragma unroll
    for (int i = 0; i < 8; i++) {
        int m_local = (i < 4) ? (ty * 4 + i) : (64 + ty * 4 + (i - 4));
        if (m_local >= rows) continue;
        int   tok = stok[m_local];
        float w   = swt[m_local];
        float* orow = out + (size_t)tok * DD + n0;
#pragma unroll
        for (int j = 0; j < 4; j++) {
            int nb = (j < 2) ? (tx * 4 + j * 2) : (64 + tx * 4 + (j - 2) * 2);
            float lo, hi;
            unpack2(c[i][j], lo, hi);
            atomicAdd(orow + nb + 0, w * (lo + bev[(j < 2) ? (j * 2)     : (4 + (j - 2) * 2)]));
            atomicAdd(orow + nb + 1, w * (hi + bev[(j < 2) ? (j * 2 + 1) : (4 + (j - 2) * 2 + 1)]));
        }
    }
}

// ---------------------------------------------------------------------------
extern "C" void kernel_launch(void* const* d_in, const int* in_sizes, int n_in,
                              void* d_out, int out_size) {
    const float* x  = (const float*)d_in[0];   // [B,S,D]
    const float* Wg = (const float*)d_in[1];   // [D,E]
    const float* bg = (const float*)d_in[2];   // [E]
    const float* We = (const float*)d_in[3];   // [E,D,D]
    const float* be = (const float*)d_in[4];   // [E,D]
    float* out = (float*)d_out;                // [B,S,D]

    cudaMemsetAsync(d_out, 0, (size_t)out_size * sizeof(float));
    reset_kernel<<<1, 32>>>();
    gate_kernel<<<NTOK / 8, 256>>>(x, Wg, bg);

    dim3 grid(DD / BN, NTOK / BM, EE);   // (8, 64, 8); empty M-tiles early-exit
    moe_gemm<<<grid, 256>>>(x, We, be, out);
}

// round 6
// speedup vs baseline: 2.4440x; 2.4440x over previous
#include <cuda_runtime.h>
#include <cuda.h>
#include <cuda_fp16.h>
#include <math.h>
#include <stdint.h>

// ---------------- problem constants ----------------
#define NTOK 8192          // B*S
#define DD   1024          // D
#define EE   8             // experts
#define BM   128           // GEMM M tile
#define BN   128           // GEMM N tile
#define BKH  64            // halves per k-chunk (128 bytes = SW128 atom row)
#define KTOT 2048          // split-K': [hi(1024) | corr(1024)]
#define NCH  (KTOT / BKH)  // 32 chunks
#define NST  4             // pipeline stages
#define TILE_BYTES 16384   // 128 rows x 128 B
#define STG_BYTES  32768   // A tile + B tile
#define SMEM_BYTES (2048 + 1024 + NST * STG_BYTES)   // 134144
#define XA_ROWS (2 * NTOK + EE * (BM - 1) + 8)       // padded gathered rows (<=17408)

#define ALPHA  0.015625f   // 2^-6
#define INVA   64.0f
#define SCALE1 0.984375f   // 1 - ALPHA

// ---------------- device scratch (allocation-free) ----------------
__device__ __align__(128) __half g_xa_h[(size_t)XA_ROWS * KTOT];  // [row][2048] ~71MB
__device__ __align__(128) __half g_wb_h[(size_t)EE * DD * KTOT];  // [e*1024+n][2048] ~33MB
__device__ int   g_cnt[EE];
__device__ int   g_padoff[EE];
__device__ int   g_tok[EE * NTOK];
__device__ float g_wt [EE * NTOK];

// ---------------- PTX helpers ----------------
__device__ __forceinline__ uint32_t smem_u32(const void* p) {
    uint32_t a;
    asm("{ .reg .u64 t; cvta.to.shared.u64 t, %1; cvt.u32.u64 %0, t; }" : "=r"(a) : "l"(p));
    return a;
}

#define SWZ(b) ((b) ^ (((b) >> 3) & 0x70))

#define MBAR_INIT(addr, cnt) \
    asm volatile("mbarrier.init.shared.b64 [%0], %1;" :: "r"(addr), "r"((uint32_t)(cnt)) : "memory")
#define MBAR_EXPECT_TX(addr, bytes) \
    asm volatile("mbarrier.arrive.expect_tx.shared.b64 _, [%0], %1;" :: "r"(addr), "r"((uint32_t)(bytes)) : "memory")
#define MBAR_ARRIVE(addr) \
    asm volatile("mbarrier.arrive.shared.b64 _, [%0];" :: "r"(addr) : "memory")

#define MBAR_WAIT(addr, parity) do {                                              \
    uint32_t _m = (addr); uint32_t _p = (parity); uint32_t _d;                    \
    asm volatile("{\n\t.reg .pred p;\n\t"                                         \
        "mbarrier.try_wait.parity.acquire.cta.shared::cta.b64 p, [%1], %2;\n\t"   \
        "selp.b32 %0, 1, 0, p;\n\t}"                                              \
        : "=r"(_d) : "r"(_m), "r"(_p) : "memory");                                \
    if (!_d) {                                                                    \
        asm volatile("{\n\t.reg .pred P1;\n\t"                                    \
        "WL_%=:\n\t"                                                              \
        "mbarrier.try_wait.parity.acquire.cta.shared::cta.b64 P1, [%0], %1, 0x989680;\n\t" \
        "@P1 bra.uni WD_%=;\n\t"                                                  \
        "bra.uni WL_%=;\n\t"                                                      \
        "WD_%=:\n\t}" :: "r"(_m), "r"(_p) : "memory");                            \
    }                                                                             \
} while (0)

#define TMA2D(dst, map, cx, cy, mbar) \
    asm volatile("cp.async.bulk.tensor.2d.shared::cta.global.tile.mbarrier::complete_tx::bytes " \
                 "[%0], [%1, {%2, %3}], [%4];" \
                 :: "r"(dst), "l"(map), "r"((int)(cx)), "r"((int)(cy)), "r"(mbar) : "memory")

#define LDSM_X4(r, addr) \
    asm volatile("ldmatrix.sync.aligned.m8n8.x4.shared.b16 {%0,%1,%2,%3}, [%4];" \
        : "=r"((r)[0]), "=r"((r)[1]), "=r"((r)[2]), "=r"((r)[3]) : "r"(addr))

__device__ __forceinline__ void mma16816(float* d, const uint32_t* a,
                                         uint32_t b0, uint32_t b1) {
    asm volatile("mma.sync.aligned.m16n8k16.row.col.f32.f16.f16.f32 "
        "{%0,%1,%2,%3}, {%4,%5,%6,%7}, {%8,%9}, {%0,%1,%2,%3};"
        : "+f"(d[0]), "+f"(d[1]), "+f"(d[2]), "+f"(d[3])
        : "r"(a[0]), "r"(a[1]), "r"(a[2]), "r"(a[3]), "r"(b0), "r"(b1));
}

// ---------------- kernel 1: reset counters ----------------
__global__ void reset_kernel() {
    if (threadIdx.x < EE) g_cnt[threadIdx.x] = 0;
}

// ---------------- kernel 2: gating / routing (one warp per token) ----------------
__global__ void gate_kernel(const float* __restrict__ x,
                            const float* __restrict__ Wg,
                            const float* __restrict__ bg) {
    int gwarp = (blockIdx.x * blockDim.x + threadIdx.x) >> 5;
    int lane  = threadIdx.x & 31;
    if (gwarp >= NTOK) return;

    const float* xr = x + (size_t)gwarp * DD;
    float acc[EE];
#pragma unroll
    for (int e = 0; e < EE; e++) acc[e] = 0.f;

    for (int d = lane; d < DD; d += 32) {
        float xv = xr[d];
        const float4* wr = reinterpret_cast<const float4*>(Wg + (size_t)d * EE);
        float4 w0 = wr[0];
        float4 w1 = wr[1];
        acc[0] += xv * w0.x; acc[1] += xv * w0.y;
        acc[2] += xv * w0.z; acc[3] += xv * w0.w;
        acc[4] += xv * w1.x; acc[5] += xv * w1.y;
        acc[6] += xv * w1.z; acc[7] += xv * w1.w;
    }
#pragma unroll
    for (int e = 0; e < EE; e++) {
#pragma unroll
        for (int off = 16; off > 0; off >>= 1)
            acc[e] += __shfl_xor_sync(0xffffffffu, acc[e], off);
    }

    if (lane == 0) {
        float s[EE];
#pragma unroll
        for (int e = 0; e < EE; e++) s[e] = acc[e] + bg[e];
        int i0 = 0;
#pragma unroll
        for (int e = 1; e < EE; e++) if (s[e] > s[i0]) i0 = e;
        int i1 = (i0 == 0) ? 1 : 0;
#pragma unroll
        for (int e = 0; e < EE; e++) if (e != i0 && s[e] > s[i1]) i1 = e;

        float w0 = 1.f / (1.f + expf(s[i1] - s[i0]));
        float w1 = 1.f - w0;

        int p0 = atomicAdd(&g_cnt[i0], 1);
        g_tok[i0 * NTOK + p0] = gwarp;
        g_wt [i0 * NTOK + p0] = w0;
        int p1 = atomicAdd(&g_cnt[i1], 1);
        g_tok[i1 * NTOK + p1] = gwarp;
        g_wt [i1 * NTOK + p1] = w1;
    }
}

// ---------------- kernel 3: padded prefix offsets ----------------
__global__ void offsets_kernel() {
    if (threadIdx.x == 0) {
        int off = 0;
        for (int e = 0; e < EE; e++) {
            g_padoff[e] = off;
            off += ((g_cnt[e] + BM - 1) / BM) * BM;
        }
    }
}

// ---------------- kernel 4: gather routed x rows -> [xh | xl + a*xh] fp16 ----------
__global__ void gather_kernel(const float* __restrict__ x) {
    int e    = blockIdx.y;
    int slot = blockIdx.x;
    if (slot >= g_cnt[e]) return;
    int tok = g_tok[e * NTOK + slot];
    const float4* src = reinterpret_cast<const float4*>(x + (size_t)tok * DD);
    size_t row = (size_t)(g_padoff[e] + slot);
    __half2* d0 = reinterpret_cast<__half2*>(g_xa_h + row * KTOT);
    __half2* d1 = reinterpret_cast<__half2*>(g_xa_h + row * KTOT + DD);
    for (int i = threadIdx.x; i < DD / 4; i += blockDim.x) {
        float4 v = src[i];
        __half h0 = __float2half_rn(v.x), h1 = __float2half_rn(v.y);
        __half h2 = __float2half_rn(v.z), h3 = __float2half_rn(v.w);
        float f0 = __half2float(h0), f1 = __half2float(h1);
        float f2 = __half2float(h2), f3 = __half2float(h3);
        __half c0 = __float2half_rn((v.x - f0) + ALPHA * f0);
        __half c1 = __float2half_rn((v.y - f1) + ALPHA * f1);
        __half c2 = __float2half_rn((v.z - f2) + ALPHA * f2);
        __half c3 = __float2half_rn((v.w - f3) + ALPHA * f3);
        d0[i * 2]     = __halves2half2(h0, h1);
        d0[i * 2 + 1] = __halves2half2(h2, h3);
        d1[i * 2]     = __halves2half2(c0, c1);
        d1[i * 2 + 1] = __halves2half2(c2, c3);
    }
}

// ---------------- kernel 5: We [e][k][n] -> g_wb_h [e][n][wh | wh + wl/a] ----------
__global__ void wconv_kernel(const float* __restrict__ We) {
    __shared__ float t[32][33];
    int e  = blockIdx.z;
    int k0 = blockIdx.x * 32;
    int n0 = blockIdx.y * 32;
    int tx = threadIdx.x, ty = threadIdx.y;  // 32 x 8
    const float* src = We + ((size_t)e << 20);
    __half* dst = g_wb_h + (size_t)e * DD * KTOT;
#pragma unroll
    for (int i = 0; i < 4; i++)
        t[ty + i * 8][tx] = src[(size_t)(k0 + ty + i * 8) * DD + n0 + tx];
    __syncthreads();
#pragma unroll
    for (int i = 0; i < 4; i++) {
        int n = n0 + ty + i * 8;
        float w = t[tx][ty + i * 8];
        __half wh = __float2half_rn(w);
        float whf = __half2float(wh);
        __half b2 = __float2half_rn(whf + INVA * (w - whf));
        dst[(size_t)n * KTOT + k0 + tx]      = wh;
        dst[(size_t)n * KTOT + DD + k0 + tx] = b2;
    }
}

// ---------------- kernel 6: TMA + mma.sync fp16 grouped GEMM --------------------
// grid (8, 64, 8), 256 threads (8 warps, 4(m) x 2(n), each 32x64).
// D = (1-a)*sum(xh*wh) + sum((xl+a*xh)*(wh+wl/a))  =  x*w + O(2^-18)
__global__ void __launch_bounds__(256, 1)
moe_gemm_hmma(const __grid_constant__ CUtensorMap tma_a,
              const __grid_constant__ CUtensorMap tma_b,
              const float* __restrict__ be,
              float* __restrict__ out) {
    int e   = blockIdx.z;
    int cnt = g_cnt[e];
    int m0  = blockIdx.y * BM;
    if (m0 >= cnt) return;
    int rows = min(BM, cnt - m0);
    int n0   = blockIdx.x * BN;
    int arow = g_padoff[e] + m0;
    int brow = e * DD + n0;

    extern __shared__ char smem[];
    uint32_t sb = smem_u32(smem);
    uint32_t FULLB  = sb;                      // 4 x 8B
    uint32_t EMPTYB = sb + 32;                 // 4 x 8B
    int*   stok = reinterpret_cast<int*>(smem + 64);
    float* swt  = reinterpret_cast<float*>(smem + 64 + 512);
    uint32_t tb = (sb + 1088 + 1023) & ~1023u; // 1KB-aligned tile base

    int tid = threadIdx.x, lane = tid & 31, wid = tid >> 5;
    int warp_m = wid & 3, warp_n = wid >> 2;

    if (tid < BM) {
        int idx = e * NTOK + m0 + tid;
        stok[tid] = (tid < rows) ? g_tok[idx] : 0;
        swt [tid] = (tid < rows) ? g_wt[idx] : 0.f;
    }
    if (tid == 0) {
        for (int s = 0; s < NST; s++) {
            MBAR_INIT(FULLB + s * 8, 1);
            MBAR_INIT(EMPTYB + s * 8, 256);
        }
    }
    __syncthreads();

    if (tid == 0) {
        for (int s = 0; s < NST; s++) {
            MBAR_EXPECT_TX(FULLB + s * 8, STG_BYTES);
            TMA2D(tb + s * STG_BYTES,              &tma_a, s * BKH, arow, FULLB + s * 8);
            TMA2D(tb + s * STG_BYTES + TILE_BYTES, &tma_b, s * BKH, brow, FULLB + s * 8);
        }
    }

    // per-thread ldmatrix byte offsets (within 128B-row tiles)
    uint32_t a_off = (uint32_t)(warp_m * 32 + (lane & 15)) * 128 + ((lane >> 4) << 4);
    uint32_t b_off = (uint32_t)(warp_n * 64 + (lane & 7) + ((lane >> 4) << 3)) * 128
                     + (((lane >> 3) & 1) << 4);

    float acc[2][8][4];
#pragma unroll
    for (int i = 0; i < 2; i++)
#pragma unroll
        for (int j = 0; j < 8; j++)
#pragma unroll
            for (int k = 0; k < 4; k++) acc[i][j][k] = 0.f;

    for (int c = 0; c < NCH; c++) {
        int s  = c & (NST - 1);
        int ph = (c >> 2) & 1;
        MBAR_WAIT(FULLB + s * 8, ph);
        if (c == NCH / 2) {   // chain boundary: D *= (1 - alpha)
#pragma unroll
            for (int i = 0; i < 2; i++)
#pragma unroll
                for (int j = 0; j < 8; j++)
#pragma unroll
                    for (int k = 0; k < 4; k++) acc[i][j][k] *= SCALE1;
        }
        uint32_t As = tb + s * STG_BYTES;
        uint32_t Bs = As + TILE_BYTES;
#pragma unroll
        for (int ks = 0; ks < 4; ks++) {
            uint32_t a[2][4], b[4][4];
            uint32_t kb = (uint32_t)ks * 32;
#pragma unroll
            for (int mt = 0; mt < 2; mt++) {
                uint32_t o = a_off + (uint32_t)mt * 2048 + kb;
                LDSM_X4(a[mt], As + SWZ(o));
            }
#pragma unroll
            for (int np = 0; np < 4; np++) {
                uint32_t o = b_off + (uint32_t)np * 2048 + kb;
                LDSM_X4(b[np], Bs + SWZ(o));
            }
#pragma unroll
            for (int mt = 0; mt < 2; mt++)
#pragma unroll
                for (int nt = 0; nt < 8; nt++)
                    mma16816(acc[mt][nt], a[mt],
                             b[nt >> 1][(nt & 1) * 2], b[nt >> 1][(nt & 1) * 2 + 1]);
        }
        MBAR_ARRIVE(EMPTYB + s * 8);
        if (tid == 0 && c + NST < NCH) {
            MBAR_WAIT(EMPTYB + s * 8, ph);
            MBAR_EXPECT_TX(FULLB + s * 8, STG_BYTES);
            TMA2D(As, &tma_a, (c + NST) * BKH, arow, FULLB + s * 8);
            TMA2D(Bs, &tma_b, (c + NST) * BKH, brow, FULLB + s * 8);
        }
    }

    // ---- epilogue: out[tok, n] += w * (acc + be[e, n]) (2 contribs/elem) ----
    const float* beg = be + (size_t)e * DD + n0;
#pragma unroll
    for (int mt = 0; mt < 2; mt++) {
#pragma unroll
        for (int rh = 0; rh < 2; rh++) {
            int ml = warp_m * 32 + mt * 16 + (lane >> 2) + rh * 8;
            if (ml < rows) {
                int   tok = stok[ml];
                float w   = swt[ml];
                float* orow = out + (size_t)tok * DD + n0;
#pragma unroll
                for (int nt = 0; nt < 8; nt++) {
                    int nl = warp_n * 64 + nt * 8 + (lane & 3) * 2;
                    atomicAdd(orow + nl,     w * (acc[mt][nt][rh * 2]     + beg[nl]));
                    atomicAdd(orow + nl + 1, w * (acc[mt][nt][rh * 2 + 1] + beg[nl + 1]));
                }
            }
        }
    }
}

// ---------------- host launch ----------------
typedef CUresult (*EncodeFn)(CUtensorMap*, CUtensorMapDataType, cuuint32_t, void*,
                             const cuuint64_t*, const cuuint64_t*, const cuuint32_t*,
                             const cuuint32_t*, CUtensorMapInterleave, CUtensorMapSwizzle,
                             CUtensorMapL2promotion, CUtensorMapFloatOOBfill);

extern "C" void kernel_launch(void* const* d_in, const int* in_sizes, int n_in,
                              void* d_out, int out_size) {
    const float* x  = (const float*)d_in[0];   // [B,S,D]
    const float* Wg = (const float*)d_in[1];   // [D,E]
    const float* bg = (const float*)d_in[2];   // [E]
    const float* We = (const float*)d_in[3];   // [E,D,D]
    const float* be = (const float*)d_in[4];   // [E,D]
    float* out = (float*)d_out;                // [B,S,D]

    EncodeFn encode = nullptr;
    cudaDriverEntryPointQueryResult qr;
    cudaGetDriverEntryPoint("cuTensorMapEncodeTiled", (void**)&encode,
                            cudaEnableDefault, &qr);

    void* xa_ptr = nullptr; cudaGetSymbolAddress(&xa_ptr, g_xa_h);
    void* wb_ptr = nullptr; cudaGetSymbolAddress(&wb_ptr, g_wb_h);

    CUtensorMap tma_a{}, tma_b{};
    {
        cuuint64_t dims[2]    = {KTOT, XA_ROWS};
        cuuint64_t strides[1] = {KTOT * sizeof(__half)};
        cuuint32_t box[2]     = {BKH, 128};
        cuuint32_t es[2]      = {1, 1};
        encode(&tma_a, CU_TENSOR_MAP_DATA_TYPE_FLOAT16, 2, xa_ptr, dims, strides, box, es,
               CU_TENSOR_MAP_INTERLEAVE_NONE, CU_TENSOR_MAP_SWIZZLE_128B,
               CU_TENSOR_MAP_L2_PROMOTION_L2_128B, CU_TENSOR_MAP_FLOAT_OOB_FILL_NONE);
    }
    {
        cuuint64_t dims[2]    = {KTOT, (cuuint64_t)EE * DD};
        cuuint64_t strides[1] = {KTOT * sizeof(__half)};
        cuuint32_t box[2]     = {BKH, 128};
        cuuint32_t es[2]      = {1, 1};
        encode(&tma_b, CU_TENSOR_MAP_DATA_TYPE_FLOAT16, 2, wb_ptr, dims, strides, box, es,
               CU_TENSOR_MAP_INTERLEAVE_NONE, CU_TENSOR_MAP_SWIZZLE_128B,
               CU_TENSOR_MAP_L2_PROMOTION_L2_128B, CU_TENSOR_MAP_FLOAT_OOB_FILL_NONE);
    }

    cudaFuncSetAttribute(moe_gemm_hmma, cudaFuncAttributeMaxDynamicSharedMemorySize, SMEM_BYTES);

    cudaMemsetAsync(d_out, 0, (size_t)out_size * sizeof(float));
    reset_kernel<<<1, 32>>>();
    gate_kernel<<<NTOK / 8, 256>>>(x, Wg, bg);
    offsets_kernel<<<1, 32>>>();
    gather_kernel<<<dim3(NTOK, EE), 128>>>(x);
    wconv_kernel<<<dim3(DD / 32, DD / 32, EE), dim3(32, 8)>>>(We);

    dim3 grid(DD / BN, NTOK / BM, EE);   // (8, 64, 8); empty M-tiles early-exit
    moe_gemm_hmma<<<grid, 256, SMEM_BYTES>>>(tma_a, tma_b, be, out);
}

// round 12
// speedup vs baseline: 2.6280x; 1.0753x over previous
#include <cuda_runtime.h>
#include <cuda.h>
#include <cuda_fp16.h>
#include <math.h>
#include <stdint.h>

// ---------------- problem constants ----------------
#define NTOK 8192          // B*S
#define DD   1024          // D
#define EE   8             // experts
#define BM   256           // GEMM M tile
#define BN   128           // GEMM N tile
#define BKH  64            // halves per k-chunk (128 bytes = SW128 atom)
#define KTOT 2048          // split-K': [hi(1024) | corr(1024)]
#define NCH  (KTOT / BKH)  // 32 chunks
#define NST  4             // pipeline stages
#define TILE_A_BYTES (BM * 128)              // 32768
#define TILE_B_BYTES (BN * 128)              // 16384
#define STG_BYTES    (TILE_A_BYTES + TILE_B_BYTES)  // 49152
#define SMEM_HDR     3072                    // barriers + stok(1KB) + swt(1KB), padded
#define SMEM_BYTES   (SMEM_HDR + 1024 + NST * STG_BYTES)   // 200704 (incl. align slack)
#define XA_ROWS (2 * NTOK + EE * 256)        // 18432 padded gathered rows

#define ALPHA  0.015625f   // 2^-6
#define INVA   64.0f
#define SCALE1 0.984375f   // 1 - ALPHA

// prep kernel partitioning
#define WCONV_BLOCKS 4096            // (16 k-strips) x (32 n-tiles) x 8 experts
#define GATHER_PER_E (NTOK / 4)      // 2048 blocks, 4 slots each
#define PREP_BLOCKS  (WCONV_BLOCKS + GATHER_PER_E * EE)   // 20480

// ---------------- device scratch (allocation-free) ----------------
__device__ __align__(128) __half g_xa_h[(size_t)XA_ROWS * KTOT];  // ~75MB
__device__ __align__(128) __half g_wb_h[(size_t)EE * DD * KTOT];  // ~33MB
__device__ int   g_cnt[EE];
__device__ int   g_padoff[EE];
__device__ int   g_tok[EE * NTOK];
__device__ float g_wt [EE * NTOK];

// ---------------- PTX helpers ----------------
__device__ __forceinline__ uint32_t smem_u32(const void* p) {
    uint32_t a;
    asm("{ .reg .u64 t; cvta.to.shared.u64 t, %1; cvt.u32.u64 %0, t; }" : "=r"(a) : "l"(p));
    return a;
}

#define SWZ(b) ((b) ^ (((b) >> 3) & 0x70))

#define MBAR_INIT(addr, cnt) \
    asm volatile("mbarrier.init.shared.b64 [%0], %1;" :: "r"(addr), "r"((uint32_t)(cnt)) : "memory")
#define MBAR_EXPECT_TX(addr, bytes) \
    asm volatile("mbarrier.arrive.expect_tx.shared.b64 _, [%0], %1;" :: "r"(addr), "r"((uint32_t)(bytes)) : "memory")
#define MBAR_ARRIVE(addr) \
    asm volatile("mbarrier.arrive.shared.b64 _, [%0];" :: "r"(addr) : "memory")

#define MBAR_WAIT(addr, parity) do {                                              \
    uint32_t _m = (addr); uint32_t _p = (parity); uint32_t _d;                    \
    asm volatile("{\n\t.reg .pred p;\n\t"                                         \
        "mbarrier.try_wait.parity.acquire.cta.shared::cta.b64 p, [%1], %2;\n\t"   \
        "selp.b32 %0, 1, 0, p;\n\t}"                                              \
        : "=r"(_d) : "r"(_m), "r"(_p) : "memory");                                \
    if (!_d) {                                                                    \
        asm volatile("{\n\t.reg .pred P1;\n\t"                                    \
        "WL_%=:\n\t"                                                              \
        "mbarrier.try_wait.parity.acquire.cta.shared::cta.b64 P1, [%0], %1, 0x989680;\n\t" \
        "@P1 bra.uni WD_%=;\n\t"                                                  \
        "bra.uni WL_%=;\n\t"                                                      \
        "WD_%=:\n\t}" :: "r"(_m), "r"(_p) : "memory");                            \
    }                                                                             \
} while (0)

#define TMA2D(dst, map, cx, cy, mbar) \
    asm volatile("cp.async.bulk.tensor.2d.shared::cta.global.tile.mbarrier::complete_tx::bytes " \
                 "[%0], [%1, {%2, %3}], [%4];" \
                 :: "r"(dst), "l"(map), "r"((int)(cx)), "r"((int)(cy)), "r"(mbar) : "memory")

#define LDSM_X4(r, addr) \
    asm volatile("ldmatrix.sync.aligned.m8n8.x4.shared.b16 {%0,%1,%2,%3}, [%4];" \
        : "=r"((r)[0]), "=r"((r)[1]), "=r"((r)[2]), "=r"((r)[3]) : "r"(addr))

__device__ __forceinline__ void mma16816(float* d, const uint32_t* a,
                                         uint32_t b0, uint32_t b1) {
    asm volatile("mma.sync.aligned.m16n8k16.row.col.f32.f16.f16.f32 "
        "{%0,%1,%2,%3}, {%4,%5,%6,%7}, {%8,%9}, {%0,%1,%2,%3};"
        : "+f"(d[0]), "+f"(d[1]), "+f"(d[2]), "+f"(d[3])
        : "r"(a[0]), "r"(a[1]), "r"(a[2]), "r"(a[3]), "r"(b0), "r"(b1));
}

// ---------------- kernel 1: reset counters ----------------
__global__ void reset_kernel() {
    if (threadIdx.x < EE) g_cnt[threadIdx.x] = 0;
}

// ---------------- kernel 2: gating / routing (one warp per token) ----------------
__global__ void gate_kernel(const float* __restrict__ x,
                            const float* __restrict__ Wg,
                            const float* __restrict__ bg) {
    int gwarp = (blockIdx.x * blockDim.x + threadIdx.x) >> 5;
    int lane  = threadIdx.x & 31;
    if (gwarp >= NTOK) return;

    const float* xr = x + (size_t)gwarp * DD;
    float acc[EE];
#pragma unroll
    for (int e = 0; e < EE; e++) acc[e] = 0.f;

    for (int d = lane; d < DD; d += 32) {
        float xv = xr[d];
        const float4* wr = reinterpret_cast<const float4*>(Wg + (size_t)d * EE);
        float4 w0 = wr[0];
        float4 w1 = wr[1];
        acc[0] += xv * w0.x; acc[1] += xv * w0.y;
        acc[2] += xv * w0.z; acc[3] += xv * w0.w;
        acc[4] += xv * w1.x; acc[5] += xv * w1.y;
        acc[6] += xv * w1.z; acc[7] += xv * w1.w;
    }
#pragma unroll
    for (int e = 0; e < EE; e++) {
#pragma unroll
        for (int off = 16; off > 0; off >>= 1)
            acc[e] += __shfl_xor_sync(0xffffffffu, acc[e], off);
    }

    if (lane == 0) {
        float s[EE];
#pragma unroll
        for (int e = 0; e < EE; e++) s[e] = acc[e] + bg[e];
        int i0 = 0;
#pragma unroll
        for (int e = 1; e < EE; e++) if (s[e] > s[i0]) i0 = e;
        int i1 = (i0 == 0) ? 1 : 0;
#pragma unroll
        for (int e = 0; e < EE; e++) if (e != i0 && s[e] > s[i1]) i1 = e;

        float w0 = 1.f / (1.f + expf(s[i1] - s[i0]));
        float w1 = 1.f - w0;

        int p0 = atomicAdd(&g_cnt[i0], 1);
        g_tok[i0 * NTOK + p0] = gwarp;
        g_wt [i0 * NTOK + p0] = w0;
        int p1 = atomicAdd(&g_cnt[i1], 1);
        g_tok[i1 * NTOK + p1] = gwarp;
        g_wt [i1 * NTOK + p1] = w1;
    }
}

// ---------------- kernel 3: padded prefix offsets ----------------
__global__ void offsets_kernel() {
    if (threadIdx.x == 0) {
        int off = 0;
        for (int e = 0; e < EE; e++) {
            g_padoff[e] = off;
            off += ((g_cnt[e] + BM - 1) / BM) * BM;
        }
    }
}

// ---------------- kernel 4: FUSED prep: wconv + gather ----------------
// Role 1 (bid < WCONV_BLOCKS): We [e][k][n] -> g_wb_h [e][n][wh | wh+wl/a]
//   tile: 64(k) x 32(n) per block.
// Role 2: gather 4 routed x rows per block -> [xh | xl + a*xh] fp16.
__global__ void __launch_bounds__(256)
prep_kernel(const float* __restrict__ x, const float* __restrict__ We) {
    int bid = blockIdx.x;
    int tid = threadIdx.x;

    if (bid < WCONV_BLOCKS) {
        __shared__ float t[64][33];
        int e  = bid >> 9;                 // 512 tiles per expert
        int r  = bid & 511;
        int k0 = (r & 15) * 64;            // 16 k-strips
        int n0 = (r >> 4) * 32;            // 32 n-tiles
        const float* src = We + ((size_t)e << 20);
        __half* dst = g_wb_h + (size_t)e * DD * KTOT;

#pragma unroll
        for (int i = 0; i < 8; i++) {
            int kk = (tid >> 5) + i * 8;   // 0..63
            int nn = tid & 31;
            t[kk][nn] = src[(size_t)(k0 + kk) * DD + n0 + nn];
        }
        __syncthreads();

        int nn  = tid >> 3;                // 0..31
        int kk0 = (tid & 7) * 8;           // 0..56
        size_t rowo = (size_t)(n0 + nn) * KTOT + k0 + kk0;
        __half hb[8], cb[8];
#pragma unroll
        for (int i = 0; i < 8; i++) {
            float w = t[kk0 + i][nn];
            __half wh = __float2half_rn(w);
            float whf = __half2float(wh);
            hb[i] = wh;
            cb[i] = __float2half_rn(whf + INVA * (w - whf));
        }
        *reinterpret_cast<uint4*>(dst + rowo)      = *reinterpret_cast<uint4*>(hb);
        *reinterpret_cast<uint4*>(dst + rowo + DD) = *reinterpret_cast<uint4*>(cb);
    } else {
        int b    = bid - WCONV_BLOCKS;
        int e    = b / GATHER_PER_E;
        int base = (b % GATHER_PER_E) * 4;
        int cnt  = g_cnt[e];
        if (base >= cnt) return;
        int slot = base + (tid >> 6);
        if (slot >= cnt) return;
        int tok = g_tok[e * NTOK + slot];
        size_t row = (size_t)(g_padoff[e] + slot);
        const float4* src = reinterpret_cast<const float4*>(x + (size_t)tok * DD);
        __half2* d0 = reinterpret_cast<__half2*>(g_xa_h + row * KTOT);
        __half2* d1 = reinterpret_cast<__half2*>(g_xa_h + row * KTOT + DD);
        int i0 = tid & 63;
#pragma unroll
        for (int j = 0; j < 4; j++) {
            int i = i0 + j * 64;           // 0..255
            float4 v = src[i];
            __half h0 = __float2half_rn(v.x), h1 = __float2half_rn(v.y);
            __half h2 = __float2half_rn(v.z), h3 = __float2half_rn(v.w);
            float f0 = __half2float(h0), f1 = __half2float(h1);
            float f2 = __half2float(h2), f3 = __half2float(h3);
            __half c0 = __float2half_rn((v.x - f0) + ALPHA * f0);
            __half c1 = __float2half_rn((v.y - f1) + ALPHA * f1);
            __half c2 = __float2half_rn((v.z - f2) + ALPHA * f2);
            __half c3 = __float2half_rn((v.w - f3) + ALPHA * f3);
            d0[i * 2]     = __halves2half2(h0, h1);
            d0[i * 2 + 1] = __halves2half2(h2, h3);
            d1[i * 2]     = __halves2half2(c0, c1);
            d1[i * 2 + 1] = __halves2half2(c2, c3);
        }
    }
}

// ---------------- kernel 5: TMA + mma.sync fp16 grouped GEMM --------------------
// 256x128 tile, 256 threads (8 warps = 4m x 2n, each 64x64).
// D = (1-a)*sum(xh*wh) + sum((xl+a*xh)*(wh+wl/a)) = x*w + O(2^-18)
__global__ void __launch_bounds__(256, 1)
moe_gemm_hmma(const __grid_constant__ CUtensorMap tma_a,
              const __grid_constant__ CUtensorMap tma_b,
              const float* __restrict__ be,
              float* __restrict__ out) {
    int e   = blockIdx.z;
    int cnt = g_cnt[e];
    int m0  = blockIdx.y * BM;
    if (m0 >= cnt) return;
    int rows = min(BM, cnt - m0);
    int n0   = blockIdx.x * BN;
    int arow = g_padoff[e] + m0;
    int brow = e * DD + n0;

    extern __shared__ char smem[];
    uint32_t sb = smem_u32(smem);
    uint32_t FULLB  = sb;                      // 4 x 8B
    uint32_t EMPTYB = sb + 32;                 // 4 x 8B
    int*   stok = reinterpret_cast<int*>(smem + 64);           // 256 ints  -> +1088
    float* swt  = reinterpret_cast<float*>(smem + 64 + 1024);  // 256 float -> +2112
    uint32_t tb = (sb + SMEM_HDR + 1023) & ~1023u;             // tile base (>= hdr end)

    int tid = threadIdx.x, lane = tid & 31, wid = tid >> 5;
    int warp_m = wid & 3, warp_n = wid >> 2;

    {
        int idx = e * NTOK + m0 + tid;
        stok[tid] = (tid < rows) ? g_tok[idx] : 0;
        swt [tid] = (tid < rows) ? g_wt[idx] : 0.f;
    }
    if (tid == 0) {
        for (int s = 0; s < NST; s++) {
            MBAR_INIT(FULLB + s * 8, 1);
            MBAR_INIT(EMPTYB + s * 8, 256);
        }
    }
    __syncthreads();

    if (tid == 0) {
        for (int s = 0; s < NST; s++) {
            MBAR_EXPECT_TX(FULLB + s * 8, STG_BYTES);
            TMA2D(tb + s * STG_BYTES,                &tma_a, s * BKH, arow, FULLB + s * 8);
            TMA2D(tb + s * STG_BYTES + TILE_A_BYTES, &tma_b, s * BKH, brow, FULLB + s * 8);
        }
    }

    // ldmatrix byte offsets within 128B-row tiles
    uint32_t a_off = (uint32_t)(warp_m * 64 + (lane & 15)) * 128 + ((lane >> 4) << 4);
    uint32_t b_off = (uint32_t)(warp_n * 64 + (lane & 7) + ((lane >> 4) << 3)) * 128
                     + (((lane >> 3) & 1) << 4);

    float acc[4][8][4];
#pragma unroll
    for (int i = 0; i < 4; i++)
#pragma unroll
        for (int j = 0; j < 8; j++)
#pragma unroll
            for (int k = 0; k < 4; k++) acc[i][j][k] = 0.f;

    for (int c = 0; c < NCH; c++) {
        int s  = c & (NST - 1);
        int ph = (c >> 2) & 1;
        MBAR_WAIT(FULLB + s * 8, ph);
        if (c == NCH / 2) {   // chain boundary: D *= (1 - alpha)
#pragma unroll
            for (int i = 0; i < 4; i++)
#pragma unroll
                for (int j = 0; j < 8; j++)
#pragma unroll
                    for (int k = 0; k < 4; k++) acc[i][j][k] *= SCALE1;
        }
        uint32_t As = tb + s * STG_BYTES;
        uint32_t Bs = As + TILE_A_BYTES;
#pragma unroll
        for (int ks = 0; ks < 4; ks++) {
            uint32_t a[4][4], b[4][4];
            uint32_t kb = (uint32_t)ks * 32;
#pragma unroll
            for (int mt = 0; mt < 4; mt++) {
                uint32_t o = a_off + (uint32_t)mt * 2048 + kb;
                LDSM_X4(a[mt], As + SWZ(o));
            }
#pragma unroll
            for (int np = 0; np < 4; np++) {
                uint32_t o = b_off + (uint32_t)np * 2048 + kb;
                LDSM_X4(b[np], Bs + SWZ(o));
            }
#pragma unroll
            for (int mt = 0; mt < 4; mt++)
#pragma unroll
                for (int nt = 0; nt < 8; nt++)
                    mma16816(acc[mt][nt], a[mt],
                             b[nt >> 1][(nt & 1) * 2], b[nt >> 1][(nt & 1) * 2 + 1]);
        }
        MBAR_ARRIVE(EMPTYB + s * 8);
        if (tid == 0 && c + NST < NCH) {
            MBAR_WAIT(EMPTYB + s * 8, ph);
            MBAR_EXPECT_TX(FULLB + s * 8, STG_BYTES);
            TMA2D(As, &tma_a, (c + NST) * BKH, arow, FULLB + s * 8);
            TMA2D(Bs, &tma_b, (c + NST) * BKH, brow, FULLB + s * 8);
        }
    }

    // ---- epilogue: out[tok, n] += w * (acc + be[e, n]) (2 contribs/elem) ----
    const float* beg = be + (size_t)e * DD + n0;
#pragma unroll
    for (int mt = 0; mt < 4; mt++) {
#pragma unroll
        for (int rh = 0; rh < 2; rh++) {
            int ml = warp_m * 64 + mt * 16 + (lane >> 2) + rh * 8;
            if (ml < rows) {
                int   tok = stok[ml];
                float w   = swt[ml];
                float* orow = out + (size_t)tok * DD + n0;
#pragma unroll
                for (int nt = 0; nt < 8; nt++) {
                    int nl = warp_n * 64 + nt * 8 + (lane & 3) * 2;
                    atomicAdd(orow + nl,     w * (acc[mt][nt][rh * 2]     + beg[nl]));
                    atomicAdd(orow + nl + 1, w * (acc[mt][nt][rh * 2 + 1] + beg[nl + 1]));
                }
            }
        }
    }
}

// ---------------- host launch ----------------
typedef CUresult (*EncodeFn)(CUtensorMap*, CUtensorMapDataType, cuuint32_t, void*,
                             const cuuint64_t*, const cuuint64_t*, const cuuint32_t*,
                             const cuuint32_t*, CUtensorMapInterleave, CUtensorMapSwizzle,
                             CUtensorMapL2promotion, CUtensorMapFloatOOBfill);

extern "C" void kernel_launch(void* const* d_in, const int* in_sizes, int n_in,
                              void* d_out, int out_size) {
    const float* x  = (const float*)d_in[0];   // [B,S,D]
    const float* Wg = (const float*)d_in[1];   // [D,E]
    const float* bg = (const float*)d_in[2];   // [E]
    const float* We = (const float*)d_in[3];   // [E,D,D]
    const float* be = (const float*)d_in[4];   // [E,D]
    float* out = (float*)d_out;                // [B,S,D]

    EncodeFn encode = nullptr;
    cudaDriverEntryPointQueryResult qr;
    cudaGetDriverEntryPoint("cuTensorMapEncodeTiled", (void**)&encode,
                            cudaEnableDefault, &qr);

    void* xa_ptr = nullptr; cudaGetSymbolAddress(&xa_ptr, g_xa_h);
    void* wb_ptr = nullptr; cudaGetSymbolAddress(&wb_ptr, g_wb_h);

    CUtensorMap tma_a{}, tma_b{};
    {
        cuuint64_t dims[2]    = {KTOT, XA_ROWS};
        cuuint64_t strides[1] = {KTOT * sizeof(__half)};
        cuuint32_t box[2]     = {BKH, BM};
        cuuint32_t es[2]      = {1, 1};
        encode(&tma_a, CU_TENSOR_MAP_DATA_TYPE_FLOAT16, 2, xa_ptr, dims, strides, box, es,
               CU_TENSOR_MAP_INTERLEAVE_NONE, CU_TENSOR_MAP_SWIZZLE_128B,
               CU_TENSOR_MAP_L2_PROMOTION_L2_128B, CU_TENSOR_MAP_FLOAT_OOB_FILL_NONE);
    }
    {
        cuuint64_t dims[2]    = {KTOT, (cuuint64_t)EE * DD};
        cuuint64_t strides[1] = {KTOT * sizeof(__half)};
        cuuint32_t box[2]     = {BKH, BN};
        cuuint32_t es[2]      = {1, 1};
        encode(&tma_b, CU_TENSOR_MAP_DATA_TYPE_FLOAT16, 2, wb_ptr, dims, strides, box, es,
               CU_TENSOR_MAP_INTERLEAVE_NONE, CU_TENSOR_MAP_SWIZZLE_128B,
               CU_TENSOR_MAP_L2_PROMOTION_L2_128B, CU_TENSOR_MAP_FLOAT_OOB_FILL_NONE);
    }

    cudaFuncSetAttribute(moe_gemm_hmma, cudaFuncAttributeMaxDynamicSharedMemorySize, SMEM_BYTES);

    cudaMemsetAsync(d_out, 0, (size_t)out_size * sizeof(float));
    reset_kernel<<<1, 32>>>();
    gate_kernel<<<NTOK / 8, 256>>>(x, Wg, bg);
    offsets_kernel<<<1, 32>>>();
    prep_kernel<<<PREP_BLOCKS, 256>>>(x, We);

    dim3 grid(DD / BN, NTOK / BM, EE);   // (8, 32, 8); empty M-tiles early-exit
    moe_gemm_hmma<<<grid, 256, SMEM_BYTES>>>(tma_a, tma_b, be, out);
}